// round 1
// baseline (speedup 1.0000x reference)
#include <cuda_runtime.h>
#include <cstddef>

// Problem constants
#define NB  4
#define NN  4096
#define DD  512
#define NCOL (NB*NN)        // 16384 rows total
#define SEG 16
#define SEGLEN 256          // SEG*SEGLEN == NN
#define CAP 32              // max nnz per segment (lambda~2.6, overflow prob ~1e-15)
#define MAXN (SEG*CAP)

// Scratch (static device memory: allocation-free per harness rules)
__device__ int   g_scnt[NCOL*SEG];
__device__ int   g_sidx[(size_t)NCOL*SEG*CAP];
__device__ float g_dvec[NCOL];
__device__ float g_buf0[(size_t)NCOL*DD];   // GEMM output (Z)
__device__ float g_buf1[(size_t)NCOL*DD];   // SpMM output (H)

// ---------------------------------------------------------------------------
// Build: scan adj columns (coalesced across threads), emit segmented CSR-ish
// index lists. a[b,i,j] nnz <=> adj[b,j,i] != 0 ; value = d_i*d_j.
// ---------------------------------------------------------------------------
__global__ __launch_bounds__(256) void build_kernel(const float* __restrict__ adj)
{
    int colg = blockIdx.x * 256 + threadIdx.x;   // global column 0..16383
    int s    = blockIdx.y;                       // segment 0..15
    int b    = colg >> 12;
    int i    = colg & (NN - 1);

    const float* base = adj + (size_t)b * NN * NN + i;  // column i, stride NN
    int j0  = s * SEGLEN;
    int cnt = 0;
    int out = (colg * SEG + s) * CAP;

    #pragma unroll 4
    for (int jj = 0; jj < SEGLEN; jj++) {
        float v = __ldg(base + (size_t)(j0 + jj) * NN);
        if (v != 0.0f) {
            if (cnt < CAP) g_sidx[out + cnt] = j0 + jj;
            cnt++;
        }
    }
    g_scnt[colg * SEG + s] = (cnt < CAP) ? cnt : CAP;
}

__global__ __launch_bounds__(256) void dcalc_kernel()
{
    int colg = blockIdx.x * 256 + threadIdx.x;
    int c = 0;
    #pragma unroll
    for (int s = 0; s < SEG; s++) c += g_scnt[colg * SEG + s];
    g_dvec[colg] = (c > 0) ? rsqrtf((float)c) : 0.0f;
}

// ---------------------------------------------------------------------------
// fp32 SGEMM: C[M,512] = A[M,512] @ B[512,512], row-major.
// 128x128 block tile, BK=8, 256 threads, 8x8 per-thread microtile.
// ---------------------------------------------------------------------------
__global__ __launch_bounds__(256) void sgemm_kernel(const float* __restrict__ A,
                                                    const float* __restrict__ B,
                                                    float* __restrict__ C)
{
    __shared__ float As[8][128];
    __shared__ float Bs[8][128];

    int tid = threadIdx.x;
    int bm  = blockIdx.y << 7;
    int bn  = blockIdx.x << 7;

    int arow = tid >> 1;           // 0..127
    int acol = (tid & 1) << 2;     // 0 or 4
    int brow = tid >> 5;           // 0..7
    int bcol = (tid & 31) << 2;    // 0..124

    int tx = tid & 15;             // col group
    int ty = tid >> 4;             // row group

    const float* Ag = A + (size_t)(bm + arow) * DD + acol;
    const float* Bg = B + (size_t)brow * DD + bn + bcol;

    float acc[8][8];
    #pragma unroll
    for (int i = 0; i < 8; i++)
        #pragma unroll
        for (int j = 0; j < 8; j++) acc[i][j] = 0.0f;

    for (int k0 = 0; k0 < DD; k0 += 8) {
        float4 a4 = *(const float4*)(Ag + k0);
        float4 b4 = *(const float4*)(Bg + (size_t)k0 * DD);

        As[acol + 0][arow] = a4.x;
        As[acol + 1][arow] = a4.y;
        As[acol + 2][arow] = a4.z;
        As[acol + 3][arow] = a4.w;
        *(float4*)&Bs[brow][bcol] = b4;
        __syncthreads();

        #pragma unroll
        for (int k = 0; k < 8; k++) {
            float a[8], bb[8];
            *(float4*)&a[0]  = *(const float4*)&As[k][ty * 8];
            *(float4*)&a[4]  = *(const float4*)&As[k][ty * 8 + 4];
            *(float4*)&bb[0] = *(const float4*)&Bs[k][tx * 8];
            *(float4*)&bb[4] = *(const float4*)&Bs[k][tx * 8 + 4];
            #pragma unroll
            for (int i = 0; i < 8; i++)
                #pragma unroll
                for (int j = 0; j < 8; j++)
                    acc[i][j] = fmaf(a[i], bb[j], acc[i][j]);
        }
        __syncthreads();
    }

    #pragma unroll
    for (int i = 0; i < 8; i++) {
        float* Crow = C + (size_t)(bm + ty * 8 + i) * DD + bn + tx * 8;
        *(float4*)Crow       = make_float4(acc[i][0], acc[i][1], acc[i][2], acc[i][3]);
        *(float4*)(Crow + 4) = make_float4(acc[i][4], acc[i][5], acc[i][6], acc[i][7]);
    }
}

// ---------------------------------------------------------------------------
// SpMM + bias + (optional) ReLU:
//   out[b,i,:] = act( d_i * sum_{j in nbr(i)} d_j * Z[b,j,:] + bias )
// One block (128 threads, float4 per thread) per output row.
// ---------------------------------------------------------------------------
__global__ __launch_bounds__(128) void spmm_kernel(const float* __restrict__ Z,
                                                   const float* __restrict__ bias,
                                                   float* __restrict__ out,
                                                   int do_relu)
{
    int row = blockIdx.x;           // 0..16383
    int b   = row >> 12;
    int tid = threadIdx.x;          // 0..127

    __shared__ int   soff[SEG + 1];
    __shared__ int   sj[MAXN];
    __shared__ float sdj[MAXN];

    if (tid == 0) {
        int o = 0;
        #pragma unroll
        for (int s = 0; s < SEG; s++) { soff[s] = o; o += g_scnt[row * SEG + s]; }
        soff[SEG] = o;
    }
    __syncthreads();

    #pragma unroll
    for (int s = 0; s < SEG; s++) {
        int o = soff[s];
        int c = soff[s + 1] - o;
        if (tid < c) {
            int j = g_sidx[((size_t)row * SEG + s) * CAP + tid];
            sj[o + tid]  = j;
            sdj[o + tid] = g_dvec[(b << 12) + j];
        }
    }
    __syncthreads();

    int   total = soff[SEG];
    float di    = g_dvec[row];
    const float4* Zb = (const float4*)(Z + (size_t)b * NN * DD);

    float4 acc = make_float4(0.f, 0.f, 0.f, 0.f);
    int k = 0;
    for (; k + 2 <= total; k += 2) {
        int   j0 = sj[k],    j1 = sj[k + 1];
        float d0 = sdj[k],   d1 = sdj[k + 1];
        float4 z0 = Zb[(size_t)j0 * (DD / 4) + tid];
        float4 z1 = Zb[(size_t)j1 * (DD / 4) + tid];
        acc.x = fmaf(d0, z0.x, fmaf(d1, z1.x, acc.x));
        acc.y = fmaf(d0, z0.y, fmaf(d1, z1.y, acc.y));
        acc.z = fmaf(d0, z0.z, fmaf(d1, z1.z, acc.z));
        acc.w = fmaf(d0, z0.w, fmaf(d1, z1.w, acc.w));
    }
    if (k < total) {
        int   j0 = sj[k];
        float d0 = sdj[k];
        float4 z0 = Zb[(size_t)j0 * (DD / 4) + tid];
        acc.x = fmaf(d0, z0.x, acc.x);
        acc.y = fmaf(d0, z0.y, acc.y);
        acc.z = fmaf(d0, z0.z, acc.z);
        acc.w = fmaf(d0, z0.w, acc.w);
    }

    float4 bb = ((const float4*)bias)[tid];
    acc.x = fmaf(acc.x, di, bb.x);
    acc.y = fmaf(acc.y, di, bb.y);
    acc.z = fmaf(acc.z, di, bb.z);
    acc.w = fmaf(acc.w, di, bb.w);
    if (do_relu) {
        acc.x = fmaxf(acc.x, 0.f);
        acc.y = fmaxf(acc.y, 0.f);
        acc.z = fmaxf(acc.z, 0.f);
        acc.w = fmaxf(acc.w, 0.f);
    }
    ((float4*)out)[(size_t)row * (DD / 4) + tid] = acc;
}

// ---------------------------------------------------------------------------
extern "C" void kernel_launch(void* const* d_in, const int* in_sizes, int n_in,
                              void* d_out, int out_size)
{
    const float* x   = (const float*)d_in[0];
    const float* adj = (const float*)d_in[1];
    const float* W1  = (const float*)d_in[2];
    const float* b1  = (const float*)d_in[3];
    const float* W2  = (const float*)d_in[4];
    const float* b2  = (const float*)d_in[5];
    const float* W3  = (const float*)d_in[6];
    const float* b3  = (const float*)d_in[7];
    float* out = (float*)d_out;

    float *buf0, *buf1;
    cudaGetSymbolAddress((void**)&buf0, g_buf0);
    cudaGetSymbolAddress((void**)&buf1, g_buf1);

    // 1) sparsify adjacency + degrees
    dim3 bgrid(NCOL / 256, SEG);
    build_kernel<<<bgrid, 256>>>(adj);
    dcalc_kernel<<<NCOL / 256, 256>>>();

    dim3 ggrid(DD / 128, NCOL / 128);   // (4, 128)

    // Layer 1: Z = X @ W1 ; H1 = relu(a @ Z + b1)
    sgemm_kernel<<<ggrid, 256>>>(x, W1, buf0);
    spmm_kernel<<<NCOL, 128>>>(buf0, b1, buf1, 1);

    // Layer 2
    sgemm_kernel<<<ggrid, 256>>>(buf1, W2, buf0);
    spmm_kernel<<<NCOL, 128>>>(buf0, b2, buf1, 1);

    // Layer 3 (no relu)
    sgemm_kernel<<<ggrid, 256>>>(buf1, W3, buf0);
    spmm_kernel<<<NCOL, 128>>>(buf0, b3, out, 0);
}

// round 3
// speedup vs baseline: 1.6143x; 1.6143x over previous
#include <cuda_runtime.h>
#include <cuda_bf16.h>
#include <cstdint>
#include <cstddef>

// Problem constants
#define NB  4
#define NN  4096
#define DD  512
#define NCOL (NB*NN)
#define SEG 16
#define SEGLEN 256
#define CAP 32
#define MAXN (SEG*CAP)

// GEMM tiling
#define BM 128
#define BN 128
#define BK 64
#define KCHUNKS 24           // 3 passes * (512/64)
#define STAGE_BYTES 32768    // A 16KB + B 16KB
#define GEMM_SMEM (2*STAGE_BYTES)

__device__ __forceinline__ uint32_t smem_u32(const void* p) {
    uint32_t a;
    asm("{ .reg .u64 t; cvta.to.shared.u64 t, %1; cvt.u32.u64 %0, t; }" : "=r"(a) : "l"(p));
    return a;
}

#define CPASYNC16(s, g) \
    asm volatile("cp.async.cg.shared.global [%0], [%1], 16;" :: "r"(s), "l"(g) : "memory")
#define CP_COMMIT() asm volatile("cp.async.commit_group;" ::: "memory")

#define LDMX4(d, a) \
    asm volatile("ldmatrix.sync.aligned.m8n8.x4.shared.b16 {%0,%1,%2,%3}, [%4];" \
        : "=r"((d)[0]), "=r"((d)[1]), "=r"((d)[2]), "=r"((d)[3]) : "r"(a))

#define MMA16816(c, a, b) \
    asm volatile("mma.sync.aligned.m16n8k16.row.col.f32.bf16.bf16.f32 " \
        "{%0,%1,%2,%3},{%4,%5,%6,%7},{%8,%9},{%0,%1,%2,%3};" \
        : "+f"((c)[0]), "+f"((c)[1]), "+f"((c)[2]), "+f"((c)[3]) \
        : "r"((a)[0]), "r"((a)[1]), "r"((a)[2]), "r"((a)[3]), "r"((b)[0]), "r"((b)[1]))

// ---------------------------------------------------------------------------
// Static scratch
// ---------------------------------------------------------------------------
__device__ int   g_scnt[NCOL*SEG];
__device__ int   g_sidx[(size_t)NCOL*SEG*CAP];
__device__ float g_dvec[NCOL];
__device__ float g_buf0[(size_t)NCOL*DD];          // GEMM output Z (fp32)
__device__ __nv_bfloat16 g_hi[(size_t)NCOL*DD];    // activation hi
__device__ __nv_bfloat16 g_lo[(size_t)NCOL*DD];    // activation lo
__device__ __nv_bfloat16 g_wh[3][(size_t)DD*DD];   // W^T hi
__device__ __nv_bfloat16 g_wl[3][(size_t)DD*DD];   // W^T lo

// ---------------------------------------------------------------------------
// Adjacency sparsify + degrees
// ---------------------------------------------------------------------------
__global__ __launch_bounds__(256) void build_kernel(const float* __restrict__ adj)
{
    int colg = blockIdx.x * 256 + threadIdx.x;
    int s    = blockIdx.y;
    int b    = colg >> 12;
    int i    = colg & (NN - 1);

    const float* base = adj + (size_t)b * NN * NN + i;
    int j0  = s * SEGLEN;
    int cnt = 0;
    int out = (colg * SEG + s) * CAP;

    #pragma unroll 4
    for (int jj = 0; jj < SEGLEN; jj++) {
        float v = __ldg(base + (size_t)(j0 + jj) * NN);
        if (v != 0.0f) {
            if (cnt < CAP) g_sidx[out + cnt] = j0 + jj;
            cnt++;
        }
    }
    g_scnt[colg * SEG + s] = (cnt < CAP) ? cnt : CAP;
}

__global__ __launch_bounds__(256) void dcalc_kernel()
{
    int colg = blockIdx.x * 256 + threadIdx.x;
    int c = 0;
    #pragma unroll
    for (int s = 0; s < SEG; s++) c += g_scnt[colg * SEG + s];
    g_dvec[colg] = (c > 0) ? rsqrtf((float)c) : 0.0f;
}

// ---------------------------------------------------------------------------
// fp32 -> (hi, lo) bf16 split
// ---------------------------------------------------------------------------
__global__ __launch_bounds__(256) void split_kernel(const float* __restrict__ src,
                                                    __nv_bfloat16* __restrict__ hi,
                                                    __nv_bfloat16* __restrict__ lo)
{
    size_t i4 = (size_t)blockIdx.x * 256 + threadIdx.x;
    float4 v = ((const float4*)src)[i4];
    float vv[4] = {v.x, v.y, v.z, v.w};
    ushort h4[4], l4[4];
    #pragma unroll
    for (int k = 0; k < 4; k++) {
        __nv_bfloat16 h = __float2bfloat16(vv[k]);
        __nv_bfloat16 l = __float2bfloat16(vv[k] - __bfloat162float(h));
        h4[k] = __bfloat16_as_ushort(h);
        l4[k] = __bfloat16_as_ushort(l);
    }
    ((ushort4*)hi)[i4] = make_ushort4(h4[0], h4[1], h4[2], h4[3]);
    ((ushort4*)lo)[i4] = make_ushort4(l4[0], l4[1], l4[2], l4[3]);
}

// W [K,N] fp32 -> W^T [N,K] bf16 hi/lo
__global__ __launch_bounds__(256) void wsplit_kernel(const float* __restrict__ W,
                                                     __nv_bfloat16* __restrict__ hiT,
                                                     __nv_bfloat16* __restrict__ loT)
{
    int idx = blockIdx.x * 256 + threadIdx.x;
    int k = idx >> 9, n = idx & 511;
    float v = __ldg(W + idx);
    __nv_bfloat16 h = __float2bfloat16(v);
    __nv_bfloat16 l = __float2bfloat16(v - __bfloat162float(h));
    hiT[(size_t)n * DD + k] = h;
    loT[(size_t)n * DD + k] = l;
}

// ---------------------------------------------------------------------------
// mma.sync split-bf16 GEMM: C[M,512] = Ah*Wh + Ah*Wl + Al*Wh (fp32 accum).
// One logical K=1536 GEMM over 24 chunks of 64; per-chunk operand pointers
// select the split pass. 128x128 CTA tile, 8 warps of 32x64, double-buffered
// cp.async, swizzled smem, ldmatrix.x4 fragments.
// ---------------------------------------------------------------------------
__global__ __launch_bounds__(256, 1) void gemm_mma(
    const __nv_bfloat16* __restrict__ Ah, const __nv_bfloat16* __restrict__ Al,
    const __nv_bfloat16* __restrict__ Wh, const __nv_bfloat16* __restrict__ Wl,
    float* __restrict__ C)
{
    extern __shared__ char smem[];
    uint32_t sbase = smem_u32(smem);
    int tid = threadIdx.x, wid = tid >> 5, lane = tid & 31;
    int bm = blockIdx.x * BM, bn = blockIdx.y * BN;
    int wm = (wid & 3) * 32, wn = (wid >> 2) * 64;

    float acc[2][8][4];
    #pragma unroll
    for (int mf = 0; mf < 2; mf++)
        #pragma unroll
        for (int nf = 0; nf < 8; nf++)
            #pragma unroll
            for (int q = 0; q < 4; q++) acc[mf][nf][q] = 0.0f;

    // prefetch chunk kk into stage kk&1
    auto prefetch = [&](int kk) {
        int p  = kk >> 3;
        int k0 = (kk & 7) * 64;
        const __nv_bfloat16* Ap = (p == 2) ? Al : Ah;
        const __nv_bfloat16* Bp = (p == 1) ? Wl : Wh;
        uint32_t st = sbase + (kk & 1) * STAGE_BYTES;
        #pragma unroll
        for (int i = 0; i < 4; i++) {
            int li = i * 256 + tid;
            int r = li >> 3, c = li & 7;
            uint32_t sa = st + r * 128 + ((c ^ (r & 7)) * 16);
            CPASYNC16(sa, Ap + (size_t)(bm + r) * DD + k0 + c * 8);
        }
        #pragma unroll
        for (int i = 0; i < 4; i++) {
            int li = i * 256 + tid;
            int r = li >> 3, c = li & 7;
            uint32_t sa = st + 16384 + r * 128 + ((c ^ (r & 7)) * 16);
            CPASYNC16(sa, Bp + (size_t)(bn + r) * DD + k0 + c * 8);
        }
        CP_COMMIT();
    };

    prefetch(0);

    for (int kk = 0; kk < KCHUNKS; kk++) {
        if (kk + 1 < KCHUNKS) {
            prefetch(kk + 1);
            asm volatile("cp.async.wait_group 1;" ::: "memory");
        } else {
            asm volatile("cp.async.wait_group 0;" ::: "memory");
        }
        __syncthreads();

        uint32_t st = sbase + (kk & 1) * STAGE_BYTES;
        #pragma unroll
        for (int ks = 0; ks < 4; ks++) {
            uint32_t a[2][4], b[8][2];
            #pragma unroll
            for (int mf = 0; mf < 2; mf++) {
                int r = wm + mf * 16 + (lane & 15);
                int c = ks * 2 + (lane >> 4);
                uint32_t ad = st + r * 128 + ((c ^ (r & 7)) * 16);
                LDMX4(a[mf], ad);
            }
            #pragma unroll
            for (int nq = 0; nq < 4; nq++) {
                int r = wn + nq * 16 + (lane & 15);
                int c = ks * 2 + (lane >> 4);
                uint32_t ad = st + 16384 + r * 128 + ((c ^ (r & 7)) * 16);
                uint32_t t[4];
                LDMX4(t, ad);
                b[nq * 2][0]     = t[0];
                b[nq * 2 + 1][0] = t[1];
                b[nq * 2][1]     = t[2];
                b[nq * 2 + 1][1] = t[3];
            }
            #pragma unroll
            for (int mf = 0; mf < 2; mf++)
                #pragma unroll
                for (int nf = 0; nf < 8; nf++)
                    MMA16816(acc[mf][nf], a[mf], b[nf]);
        }
        __syncthreads();
    }

    // Epilogue: direct fp32 stores
    #pragma unroll
    for (int mf = 0; mf < 2; mf++) {
        int r0 = bm + wm + mf * 16 + (lane >> 2);
        #pragma unroll
        for (int nf = 0; nf < 8; nf++) {
            int c0 = bn + wn + nf * 8 + (lane & 3) * 2;
            *(float2*)&C[(size_t)r0 * DD + c0]       = make_float2(acc[mf][nf][0], acc[mf][nf][1]);
            *(float2*)&C[(size_t)(r0 + 8) * DD + c0] = make_float2(acc[mf][nf][2], acc[mf][nf][3]);
        }
    }
}

// ---------------------------------------------------------------------------
// SpMM + bias (+ReLU).  mode 0: relu then split-store hi/lo bf16.
//                       mode 1: plain fp32 store (final layer).
// ---------------------------------------------------------------------------
__global__ __launch_bounds__(128) void spmm_kernel(const float* __restrict__ Z,
                                                   const float* __restrict__ bias,
                                                   float* __restrict__ outf,
                                                   __nv_bfloat16* __restrict__ outh,
                                                   __nv_bfloat16* __restrict__ outl,
                                                   int mode)
{
    int row = blockIdx.x;
    int b   = row >> 12;
    int tid = threadIdx.x;

    __shared__ int   soff[SEG + 1];
    __shared__ int   sj[MAXN];
    __shared__ float sdj[MAXN];

    if (tid == 0) {
        int o = 0;
        #pragma unroll
        for (int s = 0; s < SEG; s++) { soff[s] = o; o += g_scnt[row * SEG + s]; }
        soff[SEG] = o;
    }
    __syncthreads();

    #pragma unroll
    for (int s = 0; s < SEG; s++) {
        int o = soff[s];
        int c = soff[s + 1] - o;
        if (tid < c) {
            int j = g_sidx[((size_t)row * SEG + s) * CAP + tid];
            sj[o + tid]  = j;
            sdj[o + tid] = g_dvec[(b << 12) + j];
        }
    }
    __syncthreads();

    int   total = soff[SEG];
    float di    = g_dvec[row];
    const float4* Zb = (const float4*)(Z + (size_t)b * NN * DD);

    float4 acc = make_float4(0.f, 0.f, 0.f, 0.f);
    int k = 0;
    for (; k + 2 <= total; k += 2) {
        int   j0 = sj[k],  j1 = sj[k + 1];
        float d0 = sdj[k], d1 = sdj[k + 1];
        float4 z0 = Zb[(size_t)j0 * (DD / 4) + tid];
        float4 z1 = Zb[(size_t)j1 * (DD / 4) + tid];
        acc.x = fmaf(d0, z0.x, fmaf(d1, z1.x, acc.x));
        acc.y = fmaf(d0, z0.y, fmaf(d1, z1.y, acc.y));
        acc.z = fmaf(d0, z0.z, fmaf(d1, z1.z, acc.z));
        acc.w = fmaf(d0, z0.w, fmaf(d1, z1.w, acc.w));
    }
    if (k < total) {
        int   j0 = sj[k];
        float d0 = sdj[k];
        float4 z0 = Zb[(size_t)j0 * (DD / 4) + tid];
        acc.x = fmaf(d0, z0.x, acc.x);
        acc.y = fmaf(d0, z0.y, acc.y);
        acc.z = fmaf(d0, z0.z, acc.z);
        acc.w = fmaf(d0, z0.w, acc.w);
    }

    float4 bb = ((const float4*)bias)[tid];
    float v[4];
    v[0] = fmaf(acc.x, di, bb.x);
    v[1] = fmaf(acc.y, di, bb.y);
    v[2] = fmaf(acc.z, di, bb.z);
    v[3] = fmaf(acc.w, di, bb.w);

    if (mode == 0) {
        ushort h4[4], l4[4];
        #pragma unroll
        for (int q = 0; q < 4; q++) {
            float r = fmaxf(v[q], 0.f);
            __nv_bfloat16 h = __float2bfloat16(r);
            __nv_bfloat16 l = __float2bfloat16(r - __bfloat162float(h));
            h4[q] = __bfloat16_as_ushort(h);
            l4[q] = __bfloat16_as_ushort(l);
        }
        ((ushort4*)outh)[(size_t)row * (DD / 4) + tid] = make_ushort4(h4[0], h4[1], h4[2], h4[3]);
        ((ushort4*)outl)[(size_t)row * (DD / 4) + tid] = make_ushort4(l4[0], l4[1], l4[2], l4[3]);
    } else {
        ((float4*)outf)[(size_t)row * (DD / 4) + tid] = make_float4(v[0], v[1], v[2], v[3]);
    }
}

// ---------------------------------------------------------------------------
extern "C" void kernel_launch(void* const* d_in, const int* in_sizes, int n_in,
                              void* d_out, int out_size)
{
    const float* x   = (const float*)d_in[0];
    const float* adj = (const float*)d_in[1];
    const float* W1  = (const float*)d_in[2];
    const float* b1  = (const float*)d_in[3];
    const float* W2  = (const float*)d_in[4];
    const float* b2  = (const float*)d_in[5];
    const float* W3  = (const float*)d_in[6];
    const float* b3  = (const float*)d_in[7];
    float* out = (float*)d_out;

    float *buf0;
    __nv_bfloat16 *hi, *lo, *wh, *wl;
    cudaGetSymbolAddress((void**)&buf0, g_buf0);
    cudaGetSymbolAddress((void**)&hi,   g_hi);
    cudaGetSymbolAddress((void**)&lo,   g_lo);
    cudaGetSymbolAddress((void**)&wh,   g_wh);
    cudaGetSymbolAddress((void**)&wl,   g_wl);

    cudaFuncSetAttribute(gemm_mma, cudaFuncAttributeMaxDynamicSharedMemorySize, GEMM_SMEM);

    // 1) sparsify adjacency + degrees
    dim3 bgrid(NCOL / 256, SEG);
    build_kernel<<<bgrid, 256>>>(adj);
    dcalc_kernel<<<NCOL / 256, 256>>>();

    // 2) operand conversions
    split_kernel<<<(NCOL * DD / 4) / 256, 256>>>(x, hi, lo);
    wsplit_kernel<<<(DD * DD) / 256, 256>>>(W1, wh + 0 * (size_t)DD * DD, wl + 0 * (size_t)DD * DD);
    wsplit_kernel<<<(DD * DD) / 256, 256>>>(W2, wh + 1 * (size_t)DD * DD, wl + 1 * (size_t)DD * DD);
    wsplit_kernel<<<(DD * DD) / 256, 256>>>(W3, wh + 2 * (size_t)DD * DD, wl + 2 * (size_t)DD * DD);

    dim3 ggrid(NCOL / BM, DD / BN);   // (128, 4)

    // Layer 1
    gemm_mma<<<ggrid, 256, GEMM_SMEM>>>(hi, lo, wh, wl, buf0);
    spmm_kernel<<<NCOL, 128>>>(buf0, b1, nullptr, hi, lo, 0);
    // Layer 2
    gemm_mma<<<ggrid, 256, GEMM_SMEM>>>(hi, lo, wh + (size_t)DD * DD, wl + (size_t)DD * DD, buf0);
    spmm_kernel<<<NCOL, 128>>>(buf0, b2, nullptr, hi, lo, 0);
    // Layer 3 (no relu, fp32 out)
    gemm_mma<<<ggrid, 256, GEMM_SMEM>>>(hi, lo, wh + 2 * (size_t)DD * DD, wl + 2 * (size_t)DD * DD, buf0);
    spmm_kernel<<<NCOL, 128>>>(buf0, b3, out, nullptr, nullptr, 1);
}